// round 10
// baseline (speedup 1.0000x reference)
#include <cuda_runtime.h>
#include <cuda_bf16.h>
#include <cstdint>
#include <math.h>

#define B_   16
#define TQ   512
#define TK   1024
#define DD   512

typedef __nv_bfloat16 bf16;

// ---------------- device scratch (no allocation allowed) ----------------
__device__ bf16 g_qh [(size_t)B_*TQ*DD], g_ql [(size_t)B_*TQ*DD];   // query split
__device__ bf16 g_wh [DD*DD],            g_wl [DD*DD];              // Wq split
__device__ bf16 g_kh [(size_t)B_*TK*DD], g_kl [(size_t)B_*TK*DD];   // keys split   [B,TK,DD]
__device__ bf16 g_kth[(size_t)B_*DD*TK], g_ktl[(size_t)B_*DD*TK];   // keys^T split [B,DD,TK]
__device__ bf16 g_qph[(size_t)B_*TQ*DD], g_qpl[(size_t)B_*TQ*DD];   // Q' split
__device__ bf16 g_ah [(size_t)B_*TQ*TK], g_al [(size_t)B_*TQ*TK];   // attn split

// ---------------- helpers ----------------
__device__ __forceinline__ uint32_t smem_u32(const void* p) {
    uint32_t a;
    asm("{ .reg .u64 t; cvta.to.shared.u64 t, %1; cvt.u32.u64 %0, t; }" : "=r"(a) : "l"(p));
    return a;
}
#define SW128(o) ((o) ^ (((o) >> 3) & 0x70))

__device__ __forceinline__ void cpa16(uint32_t dst, const void* src) {
    asm volatile("cp.async.cg.shared.global [%0], [%1], 16;" :: "r"(dst), "l"(src));
}
__device__ __forceinline__ void cpa_commit() {
    asm volatile("cp.async.commit_group;" ::: "memory");
}
__device__ __forceinline__ void cpa_wait(int n_newer) {
    if (n_newer >= 2)      asm volatile("cp.async.wait_group 2;" ::: "memory");
    else if (n_newer == 1) asm volatile("cp.async.wait_group 1;" ::: "memory");
    else                   asm volatile("cp.async.wait_group 0;" ::: "memory");
}
__device__ __forceinline__ void ldsm4(uint32_t* r, uint32_t addr) {
    asm volatile("ldmatrix.sync.aligned.m8n8.x4.shared.b16 {%0,%1,%2,%3}, [%4];"
                 : "=r"(r[0]), "=r"(r[1]), "=r"(r[2]), "=r"(r[3]) : "r"(addr));
}
__device__ __forceinline__ void mma16816(float* d, const uint32_t* a,
                                         uint32_t b0, uint32_t b1) {
    asm volatile(
        "mma.sync.aligned.m16n8k16.row.col.f32.bf16.bf16.f32 "
        "{%0,%1,%2,%3}, {%4,%5,%6,%7}, {%8,%9}, {%0,%1,%2,%3};"
        : "+f"(d[0]), "+f"(d[1]), "+f"(d[2]), "+f"(d[3])
        : "r"(a[0]), "r"(a[1]), "r"(a[2]), "r"(a[3]), "r"(b0), "r"(b1));
}

// ---------------- split kernels ----------------
__global__ void __launch_bounds__(256)
split_kernel(const float* __restrict__ x, bf16* __restrict__ hi,
             bf16* __restrict__ lo, int n4)
{
    int i = blockIdx.x * 256 + threadIdx.x;
    if (i >= n4) return;
    float4 v = ((const float4*)x)[i];
    union { bf16 b[4]; uint2 u; } H, L;
    float xs[4] = {v.x, v.y, v.z, v.w};
    #pragma unroll
    for (int j = 0; j < 4; j++) {
        bf16 h = __float2bfloat16(xs[j]);
        H.b[j] = h;
        L.b[j] = __float2bfloat16(xs[j] - __bfloat162float(h));
    }
    ((uint2*)hi)[i] = H.u;
    ((uint2*)lo)[i] = L.u;
}

// keys [B,TK,DD] -> split [B,TK,DD] AND transposed split [B,DD,TK], one read
__global__ void __launch_bounds__(256)
ksplit_kernel(const float* __restrict__ x,
              bf16* __restrict__ kh, bf16* __restrict__ kl,
              bf16* __restrict__ th, bf16* __restrict__ tl)
{
    __shared__ float t[32][33];
    int b = blockIdx.z;
    int k0 = blockIdx.x * 32, d0 = blockIdx.y * 32;
    const float* xb = x + (size_t)b * TK * DD;
    int tx = threadIdx.x & 31, ty = threadIdx.x >> 5;  // 32 x 8
    #pragma unroll
    for (int i = 0; i < 32; i += 8) {
        float v = xb[(size_t)(k0 + ty + i) * DD + d0 + tx];
        t[ty + i][tx] = v;
        bf16 h = __float2bfloat16(v);
        size_t o = (size_t)b * TK * DD + (size_t)(k0 + ty + i) * DD + d0 + tx;
        kh[o] = h;
        kl[o] = __float2bfloat16(v - __bfloat162float(h));
    }
    __syncthreads();
    #pragma unroll
    for (int i = 0; i < 32; i += 8) {
        float v = t[tx][ty + i];
        bf16 h = __float2bfloat16(v);
        size_t o = (size_t)b * DD * TK + (size_t)(d0 + ty + i) * TK + k0 + tx;
        th[o] = h;
        tl[o] = __float2bfloat16(v - __bfloat162float(h));
    }
}

// ---------------- 3-term split-bf16 HMMA NT GEMM ----------------
// C[m,n] = alpha * sum_k A[m,k]*B[n,k] (+bias[n]); A,B bf16 (hi,lo), k-contiguous.
// Tile 128x64xBK32, 256 thr, 8 warps (4m x 2n, warp tile 32x32),
// 4-stage cp.async (one __syncthreads per chunk), SW128 smem, 2 CTAs/SM.
// Packed smem: two 64B logical k-rows per 128B physical row.
// OUT_MODE 0: fp32 C. OUT_MODE 1: split-bf16 (Ch, Cl).
// LEN_MODE 0: none. 1: skip CTA if n0 >= len[z]. 2: truncate K to ceil32(len[z]).
#define STAGE   24576        // Ah 8K | Al 8K | Bh 4K | Bl 4K
#define NSTAGE  4
#define SMEM_DYN (NSTAGE * STAGE)

// A: 128 logical rows x 32 cols (64B). phys_row = m&63, half = m>>6.
__device__ __forceinline__ uint32_t a_off(int m, int u16) {
    return SW128((uint32_t)(((m & 63) << 7) | ((m >> 6) << 6) | (u16 << 4)));
}
// B: 64 logical rows x 32 cols. phys_row = n&31, half = n>>5.
__device__ __forceinline__ uint32_t b_off(int n, int u16) {
    return SW128((uint32_t)(((n & 31) << 7) | ((n >> 5) << 6) | (u16 << 4)));
}

template<int OUT_MODE, int LEN_MODE>
__global__ void __launch_bounds__(256, 2)
mma_gemm(const bf16* __restrict__ Ah, const bf16* __restrict__ Al, long long sA, int lda,
         const bf16* __restrict__ Bh, const bf16* __restrict__ Bl, long long sB, int ldb,
         float* __restrict__ C, bf16* __restrict__ Ch, bf16* __restrict__ Cl,
         long long sC, int ldc, int K,
         const float* __restrict__ bias, const float* __restrict__ scale,
         const int* __restrict__ lens)
{
    extern __shared__ char smem[];
    const uint32_t sbase = smem_u32(smem);
    const int tid = threadIdx.x;

    const int m0 = blockIdx.y * 128, n0 = blockIdx.x * 64;

    if (LEN_MODE == 1) {
        if (n0 >= lens[blockIdx.z]) return;   // softmax zeros+overwrites this region
    }
    int Keff = K;
    if (LEN_MODE == 2) {
        Keff = (lens[blockIdx.z] + 31) & ~31; // attn == 0 beyond len: skip chunks
    }

    Ah += (long long)blockIdx.z * sA;  Al += (long long)blockIdx.z * sA;
    Bh += (long long)blockIdx.z * sB;  Bl += (long long)blockIdx.z * sB;

    const bf16* pAh = Ah + (size_t)m0 * lda;
    const bf16* pAl = Al + (size_t)m0 * lda;
    const bf16* pBh = Bh + (size_t)n0 * ldb;
    const bf16* pBl = Bl + (size_t)n0 * ldb;

    const int NC = Keff >> 5;   // 32-wide chunks

    // ---- loader: chunk c (32 k-cols) into stage s ----
    auto load_chunk = [&](int c, int s) {
        const uint32_t base = sbase + s * STAGE;
        const size_t ck = (size_t)c * 32;
        #pragma unroll
        for (int i = 0; i < 2; i++) {              // A: 512 16B-units per array
            int v = tid + i * 256;
            int m = v >> 2, u = v & 3;
            uint32_t off = a_off(m, u);
            const size_t g = (size_t)m * lda + ck + u * 8;
            cpa16(base +        off, pAh + g);
            cpa16(base + 8192 + off, pAl + g);
        }
        {                                          // B: 256 16B-units per array
            int v = tid;
            int n = v >> 2, u = v & 3;
            uint32_t off = b_off(n, u);
            const size_t g = (size_t)n * ldb + ck + u * 8;
            cpa16(base + 16384 + off, pBh + g);
            cpa16(base + 20480 + off, pBl + g);
        }
        cpa_commit();
    };

    const int lane = tid & 31;
    const int wid = tid >> 5, wm = wid >> 1, wn = wid & 1;   // 4m x 2n
    const int arow = wm * 32 + (lane & 15);
    const int brow = wn * 32 + (lane & 15);
    const int chalf = lane >> 4;

    float acc[2][4][4];
    #pragma unroll
    for (int i = 0; i < 2; i++)
        #pragma unroll
        for (int j = 0; j < 4; j++)
            #pragma unroll
            for (int e = 0; e < 4; e++) acc[i][j][e] = 0.0f;

    // prologue: 3 chunks in flight
    #pragma unroll
    for (int p = 0; p < NSTAGE - 1; p++)
        if (p < NC) load_chunk(p, p);

    for (int c = 0; c < NC; c++) {
        const int s = c & (NSTAGE - 1);
        cpa_wait(min(NSTAGE - 2, NC - 1 - c));
        __syncthreads();
        if (c + NSTAGE - 1 < NC)
            load_chunk(c + NSTAGE - 1, (c + NSTAGE - 1) & (NSTAGE - 1));

        const uint32_t SAh = sbase + s * STAGE;
        const uint32_t SAl = SAh + 8192;
        const uint32_t SBh = SAh + 16384;
        const uint32_t SBl = SAh + 20480;

        #pragma unroll
        for (int kt = 0; kt < 2; kt++) {
            const int u16 = kt * 2 + chalf;        // 16B unit within 64B k-row
            uint32_t a_h[2][4], a_l[2][4], b_h[2][4], b_l[2][4];
            #pragma unroll
            for (int mt = 0; mt < 2; mt++) {
                uint32_t off = a_off(arow + mt * 16, u16);
                ldsm4(a_h[mt], SAh + off);
                ldsm4(a_l[mt], SAl + off);
            }
            #pragma unroll
            for (int ng = 0; ng < 2; ng++) {
                uint32_t off = b_off(brow + ng * 16, u16);
                ldsm4(b_h[ng], SBh + off);
                ldsm4(b_l[ng], SBl + off);
            }
            // term-outer ordering: same-acc MMAs are 8 issues apart
            #pragma unroll
            for (int mt = 0; mt < 2; mt++)
                #pragma unroll
                for (int nt = 0; nt < 4; nt++) {
                    const int ng = nt >> 1, sel = nt & 1;
                    mma16816(acc[mt][nt], a_h[mt], b_h[ng][sel], b_h[ng][sel + 2]);
                }
            #pragma unroll
            for (int mt = 0; mt < 2; mt++)
                #pragma unroll
                for (int nt = 0; nt < 4; nt++) {
                    const int ng = nt >> 1, sel = nt & 1;
                    mma16816(acc[mt][nt], a_h[mt], b_l[ng][sel], b_l[ng][sel + 2]);
                }
            #pragma unroll
            for (int mt = 0; mt < 2; mt++)
                #pragma unroll
                for (int nt = 0; nt < 4; nt++) {
                    const int ng = nt >> 1, sel = nt & 1;
                    mma16816(acc[mt][nt], a_l[mt], b_h[ng][sel], b_h[ng][sel + 2]);
                }
        }
    }

    // ---- epilogue ----
    const float alpha = scale ? __ldg(scale) : 1.0f;
    const int mrow = m0 + wm * 32 + (lane >> 2);
    #pragma unroll
    for (int mt = 0; mt < 2; mt++) {
        #pragma unroll
        for (int nt = 0; nt < 4; nt++) {
            const int n = n0 + wn * 32 + nt * 8 + 2 * (lane & 3);
            const float bv0 = bias ? bias[n]     : 0.0f;
            const float bv1 = bias ? bias[n + 1] : 0.0f;
            #pragma unroll
            for (int h = 0; h < 2; h++) {
                const long long m = (long long)(mrow + mt * 16 + h * 8);
                const float v0 = acc[mt][nt][2 * h + 0] * alpha + bv0;
                const float v1 = acc[mt][nt][2 * h + 1] * alpha + bv1;
                const size_t idx = (size_t)blockIdx.z * sC + m * ldc + n;
                if (OUT_MODE == 0) {
                    *(float2*)(C + idx) = make_float2(v0, v1);
                } else {
                    bf16 h0 = __float2bfloat16(v0), h1 = __float2bfloat16(v1);
                    bf16 l0 = __float2bfloat16(v0 - __bfloat162float(h0));
                    bf16 l1 = __float2bfloat16(v1 - __bfloat162float(h1));
                    *(__nv_bfloat162*)(Ch + idx) = __nv_bfloat162(h0, h1);
                    *(__nv_bfloat162*)(Cl + idx) = __nv_bfloat162(l0, l1);
                }
            }
        }
    }
}

// ---------------- softmax: warp/row, masked, writes fp32 + split bf16 ----------------
__global__ void __launch_bounds__(128)
softmax_kernel(float* __restrict__ attn, const int* __restrict__ lens,
               bf16* __restrict__ ah, bf16* __restrict__ al)
{
    int warp = (int)((blockIdx.x * blockDim.x + threadIdx.x) >> 5);
    int lane = threadIdx.x & 31;
    if (warp >= B_ * TQ) return;
    const int len = lens[warp / TQ];
    float4* row = (float4*)(attn + (size_t)warp * TK);

    float4 v[8];
    float mx = -INFINITY;
    #pragma unroll
    for (int i = 0; i < 8; i++) {
        v[i] = row[i * 32 + lane];
        int k = 4 * (i * 32 + lane);
        if (k + 0 < len) mx = fmaxf(mx, v[i].x);
        if (k + 1 < len) mx = fmaxf(mx, v[i].y);
        if (k + 2 < len) mx = fmaxf(mx, v[i].z);
        if (k + 3 < len) mx = fmaxf(mx, v[i].w);
    }
    #pragma unroll
    for (int o = 16; o > 0; o >>= 1)
        mx = fmaxf(mx, __shfl_xor_sync(0xFFFFFFFFu, mx, o));

    float sum = 0.0f;
    #pragma unroll
    for (int i = 0; i < 8; i++) {
        int k = 4 * (i * 32 + lane);
        v[i].x = (k + 0 < len) ? expf(v[i].x - mx) : 0.0f;
        v[i].y = (k + 1 < len) ? expf(v[i].y - mx) : 0.0f;
        v[i].z = (k + 2 < len) ? expf(v[i].z - mx) : 0.0f;
        v[i].w = (k + 3 < len) ? expf(v[i].w - mx) : 0.0f;
        sum += v[i].x + v[i].y + v[i].z + v[i].w;
    }
    #pragma unroll
    for (int o = 16; o > 0; o >>= 1)
        sum += __shfl_xor_sync(0xFFFFFFFFu, sum, o);

    const float inv = 1.0f / sum;
    uint2* rh = (uint2*)(ah + (size_t)warp * TK);
    uint2* rl = (uint2*)(al + (size_t)warp * TK);
    #pragma unroll
    for (int i = 0; i < 8; i++) {
        v[i].x *= inv; v[i].y *= inv; v[i].z *= inv; v[i].w *= inv;
        row[i * 32 + lane] = v[i];
        union { bf16 b[4]; uint2 u; } H, L;
        float xs[4] = {v[i].x, v[i].y, v[i].z, v[i].w};
        #pragma unroll
        for (int j = 0; j < 4; j++) {
            bf16 h = __float2bfloat16(xs[j]);
            H.b[j] = h;
            L.b[j] = __float2bfloat16(xs[j] - __bfloat162float(h));
        }
        rh[i * 32 + lane] = H.u;
        rl[i * 32 + lane] = L.u;
    }
}

// ---------------- launch ----------------
extern "C" void kernel_launch(void* const* d_in, const int* in_sizes, int n_in,
                              void* d_out, int out_size)
{
    const float *query = nullptr, *keys = nullptr, *Wq = nullptr,
                *bq = nullptr, *scale = nullptr;
    const int *lens = nullptr;
    for (int i = 0; i < n_in; i++) {
        switch (in_sizes[i]) {
            case B_ * TQ * DD: query = (const float*)d_in[i]; break;
            case B_ * TK * DD: keys  = (const float*)d_in[i]; break;
            case B_:           lens  = (const int*)  d_in[i]; break;
            case DD * DD:      Wq    = (const float*)d_in[i]; break;
            case DD:           bq    = (const float*)d_in[i]; break;
            case 1:            scale = (const float*)d_in[i]; break;
            default: break;
        }
    }

    bf16 *qh, *ql, *wh, *wl, *kh, *kl, *kth, *ktl, *qph, *qpl, *ah, *al;
    cudaGetSymbolAddress((void**)&qh,  g_qh);  cudaGetSymbolAddress((void**)&ql,  g_ql);
    cudaGetSymbolAddress((void**)&wh,  g_wh);  cudaGetSymbolAddress((void**)&wl,  g_wl);
    cudaGetSymbolAddress((void**)&kh,  g_kh);  cudaGetSymbolAddress((void**)&kl,  g_kl);
    cudaGetSymbolAddress((void**)&kth, g_kth); cudaGetSymbolAddress((void**)&ktl, g_ktl);
    cudaGetSymbolAddress((void**)&qph, g_qph); cudaGetSymbolAddress((void**)&qpl, g_qpl);
    cudaGetSymbolAddress((void**)&ah,  g_ah);  cudaGetSymbolAddress((void**)&al,  g_al);

    cudaFuncSetAttribute(mma_gemm<0,1>, cudaFuncAttributeMaxDynamicSharedMemorySize, SMEM_DYN);
    cudaFuncSetAttribute(mma_gemm<0,2>, cudaFuncAttributeMaxDynamicSharedMemorySize, SMEM_DYN);
    cudaFuncSetAttribute(mma_gemm<1,0>, cudaFuncAttributeMaxDynamicSharedMemorySize, SMEM_DYN);

    float* context = (float*)d_out;                         // B*TQ*DD
    float* attn    = (float*)d_out + (size_t)B_ * TQ * DD;  // B*TQ*TK

    // input splits
    split_kernel<<<(B_ * TQ * DD / 4 + 255) / 256, 256>>>(query, qh, ql, B_ * TQ * DD / 4);
    split_kernel<<<(DD * DD / 4 + 255) / 256, 256>>>(Wq, wh, wl, DD * DD / 4);
    ksplit_kernel<<<dim3(TK / 32, DD / 32, B_), 256>>>(keys, kh, kl, kth, ktl);

    // 1) Q' = query @ Wq^T + bq -> split bf16 directly (M=8192, N=512, K=512)
    mma_gemm<1,0><<<dim3(DD / 64, (B_ * TQ) / 128, 1), 256, SMEM_DYN>>>(
        qh, ql, 0, DD, wh, wl, 0, DD,
        nullptr, qph, qpl, 0, DD, DD, bq, nullptr, nullptr);

    // 2) scores = scale * Q'_b @ K_b^T -> fp32 attn; skip fully-masked N tiles
    mma_gemm<0,1><<<dim3(TK / 64, TQ / 128, B_), 256, SMEM_DYN>>>(
        qph, qpl, (long long)TQ * DD, DD,
        kh, kl, (long long)TK * DD, DD,
        attn, nullptr, nullptr, (long long)TQ * TK, TK, DD, nullptr, scale, lens);

    // 3) masked softmax (fp32 out + fused split; zeros all masked columns)
    softmax_kernel<<<(B_ * TQ * 32) / 128, 128>>>(attn, lens, ah, al);

    // 4) context = attn_b @ keysT_b^T -> fp32; truncate K to valid length
    mma_gemm<0,2><<<dim3(DD / 64, TQ / 128, B_), 256, SMEM_DYN>>>(
        ah, al, (long long)TQ * TK, TK,
        kth, ktl, (long long)DD * TK, TK,
        context, nullptr, nullptr, (long long)TQ * DD, DD, TK, nullptr, nullptr, lens);
}

// round 11
// speedup vs baseline: 1.0186x; 1.0186x over previous
#include <cuda_runtime.h>
#include <cuda_bf16.h>
#include <cstdint>
#include <math.h>

#define B_   16
#define TQ   512
#define TK   1024
#define DD   512

typedef __nv_bfloat16 bf16;

// ---------------- device scratch (no allocation allowed) ----------------
__device__ bf16 g_qh [(size_t)B_*TQ*DD], g_ql [(size_t)B_*TQ*DD];   // query split
__device__ bf16 g_wh [DD*DD],            g_wl [DD*DD];              // Wq split
__device__ bf16 g_kh [(size_t)B_*TK*DD], g_kl [(size_t)B_*TK*DD];   // keys split   [B,TK,DD]
__device__ bf16 g_kth[(size_t)B_*DD*TK], g_ktl[(size_t)B_*DD*TK];   // keys^T split [B,DD,TK]
__device__ bf16 g_qph[(size_t)B_*TQ*DD], g_qpl[(size_t)B_*TQ*DD];   // Q' split
__device__ bf16 g_ah [(size_t)B_*TQ*TK], g_al [(size_t)B_*TQ*TK];   // attn split

// ---------------- helpers ----------------
__device__ __forceinline__ uint32_t smem_u32(const void* p) {
    uint32_t a;
    asm("{ .reg .u64 t; cvta.to.shared.u64 t, %1; cvt.u32.u64 %0, t; }" : "=r"(a) : "l"(p));
    return a;
}
#define SW128(o) ((o) ^ (((o) >> 3) & 0x70))

__device__ __forceinline__ void cpa16(uint32_t dst, const void* src) {
    asm volatile("cp.async.cg.shared.global [%0], [%1], 16;" :: "r"(dst), "l"(src));
}
__device__ __forceinline__ void cpa_commit() {
    asm volatile("cp.async.commit_group;" ::: "memory");
}
__device__ __forceinline__ void ldsm4(uint32_t* r, uint32_t addr) {
    asm volatile("ldmatrix.sync.aligned.m8n8.x4.shared.b16 {%0,%1,%2,%3}, [%4];"
                 : "=r"(r[0]), "=r"(r[1]), "=r"(r[2]), "=r"(r[3]) : "r"(addr));
}
__device__ __forceinline__ void mma16816(float* d, const uint32_t* a,
                                         uint32_t b0, uint32_t b1) {
    asm volatile(
        "mma.sync.aligned.m16n8k16.row.col.f32.bf16.bf16.f32 "
        "{%0,%1,%2,%3}, {%4,%5,%6,%7}, {%8,%9}, {%0,%1,%2,%3};"
        : "+f"(d[0]), "+f"(d[1]), "+f"(d[2]), "+f"(d[3])
        : "r"(a[0]), "r"(a[1]), "r"(a[2]), "r"(a[3]), "r"(b0), "r"(b1));
}
__device__ __forceinline__ void split4(float4 v, uint2& hu, uint2& lu) {
    union { bf16 b[4]; uint2 u; } H, L;
    float xs[4] = {v.x, v.y, v.z, v.w};
    #pragma unroll
    for (int j = 0; j < 4; j++) {
        bf16 h = __float2bfloat16(xs[j]);
        H.b[j] = h;
        L.b[j] = __float2bfloat16(xs[j] - __bfloat162float(h));
    }
    hu = H.u; lu = L.u;
}

// ---------------- split kernel (query / Wq) ----------------
__global__ void __launch_bounds__(256)
split_kernel(const float* __restrict__ x, bf16* __restrict__ hi,
             bf16* __restrict__ lo, int n4)
{
    int i = blockIdx.x * 256 + threadIdx.x;
    if (i >= n4) return;
    float4 v = ((const float4*)x)[i];
    uint2 hu, lu;
    split4(v, hu, lu);
    ((uint2*)hi)[i] = hu;
    ((uint2*)lo)[i] = lu;
}

// ---------------- round-9-proven GEMM body (BK=64, 2-stage) ----------------
// C[m,n] = alpha * sum_k A[m,k]*B[n,k] (+bias[n]); A,B bf16 (hi,lo), k-contiguous.
// Tile 128x64xBK64, 256 thr, 8 warps (4m x 2n), SW128 smem, 2 CTAs/SM.
// OUT_MODE 0: fp32 C. OUT_MODE 1: split-bf16 (Ch, Cl).
// LEN_MODE 0: none. 1: skip if n0 >= len. 2: truncate K to ceil64(len).
#define STAGE 49152          // Ah 16K | Al 16K | Bh 8K | Bl 8K
#define SMEM_DYN (2 * STAGE)

template<int OUT_MODE, int LEN_MODE>
__device__ __forceinline__ void
gemm_body(char* smem, int m0, int n0, int bz,
          const bf16* __restrict__ Ah, const bf16* __restrict__ Al, long long sA, int lda,
          const bf16* __restrict__ Bh, const bf16* __restrict__ Bl, long long sB, int ldb,
          float* __restrict__ C, bf16* __restrict__ Ch, bf16* __restrict__ Cl,
          long long sC, int ldc, int K,
          const float* __restrict__ bias, const float* __restrict__ scale,
          const int* __restrict__ lens)
{
    const uint32_t sbase = smem_u32(smem);
    const int tid = threadIdx.x;

    if (LEN_MODE == 1) {
        if (n0 >= lens[bz]) return;           // softmax zeros+overwrites this region
    }
    int Keff = K;
    if (LEN_MODE == 2) {
        Keff = (lens[bz] + 63) & ~63;         // attn == 0 beyond len: skip chunks
    }

    Ah += (long long)bz * sA;  Al += (long long)bz * sA;
    Bh += (long long)bz * sB;  Bl += (long long)bz * sB;

    const bf16* pAh = Ah + (size_t)m0 * lda;
    const bf16* pAl = Al + (size_t)m0 * lda;
    const bf16* pBh = Bh + (size_t)n0 * ldb;
    const bf16* pBl = Bl + (size_t)n0 * ldb;

    const int NC = Keff >> 6;

    auto load_chunk = [&](int c, int s) {
        const uint32_t base = sbase + s * STAGE;
        const size_t ck = (size_t)c * 64;
        #pragma unroll
        for (int i = 0; i < 4; i++) {              // A: 128 rows x 8 units
            int u = tid + i * 256;
            int row = u >> 3, c8 = u & 7;
            uint32_t off = SW128((uint32_t)((row << 7) | (c8 << 4)));
            const size_t g = (size_t)row * lda + ck + c8 * 8;
            cpa16(base +         off, pAh + g);
            cpa16(base + 16384 + off, pAl + g);
        }
        #pragma unroll
        for (int i = 0; i < 2; i++) {              // B: 64 rows x 8 units
            int u = tid + i * 256;
            int row = u >> 3, c8 = u & 7;
            uint32_t off = SW128((uint32_t)((row << 7) | (c8 << 4)));
            const size_t g = (size_t)row * ldb + ck + c8 * 8;
            cpa16(base + 32768 + off, pBh + g);
            cpa16(base + 40960 + off, pBl + g);
        }
        cpa_commit();
    };

    const int lane = tid & 31;
    const int wid = tid >> 5, wm = wid >> 1, wn = wid & 1;   // 4m x 2n
    const uint32_t arow = (uint32_t)(wm * 32 + (lane & 15));
    const uint32_t brow = (uint32_t)(wn * 32 + (lane & 15));
    const uint32_t chalf = (uint32_t)(lane >> 4);

    float acc[2][4][4];
    #pragma unroll
    for (int i = 0; i < 2; i++)
        #pragma unroll
        for (int j = 0; j < 4; j++)
            #pragma unroll
            for (int e = 0; e < 4; e++) acc[i][j][e] = 0.0f;

    uint32_t a_h[2][2][4], a_l[2][2][4], b_h[2][2][4], b_l[2][2][4];

    auto load_frags = [&](uint32_t SAh, uint32_t SAl, uint32_t SBh, uint32_t SBl,
                          int kt, int p) {
        const uint32_t ck16 = (uint32_t)((kt * 2 + chalf) << 4);
        #pragma unroll
        for (int mt = 0; mt < 2; mt++) {
            uint32_t off = SW128((uint32_t)(((arow + mt * 16) << 7) | ck16));
            ldsm4(a_h[p][mt], SAh + off);
            ldsm4(a_l[p][mt], SAl + off);
        }
        #pragma unroll
        for (int ng = 0; ng < 2; ng++) {
            uint32_t off = SW128((uint32_t)(((brow + ng * 16) << 7) | ck16));
            ldsm4(b_h[p][ng], SBh + off);
            ldsm4(b_l[p][ng], SBl + off);
        }
    };

    load_chunk(0, 0);

    for (int c = 0; c < NC; c++) {
        const int s = c & 1;
        if (c + 1 < NC) {
            load_chunk(c + 1, s ^ 1);
            asm volatile("cp.async.wait_group 1;" ::: "memory");
        } else {
            asm volatile("cp.async.wait_group 0;" ::: "memory");
        }
        __syncthreads();

        const uint32_t SAh = sbase + s * STAGE;
        const uint32_t SAl = SAh + 16384;
        const uint32_t SBh = SAh + 32768;
        const uint32_t SBl = SAh + 40960;

        load_frags(SAh, SAl, SBh, SBl, 0, 0);
        #pragma unroll
        for (int kt = 0; kt < 4; kt++) {
            const int cur = kt & 1;
            if (kt < 3) load_frags(SAh, SAl, SBh, SBl, kt + 1, cur ^ 1);
            #pragma unroll
            for (int mt = 0; mt < 2; mt++)
                #pragma unroll
                for (int nt = 0; nt < 4; nt++) {
                    const int ng = nt >> 1, sel = nt & 1;
                    mma16816(acc[mt][nt], a_h[cur][mt],
                             b_h[cur][ng][sel], b_h[cur][ng][sel + 2]);
                }
            #pragma unroll
            for (int mt = 0; mt < 2; mt++)
                #pragma unroll
                for (int nt = 0; nt < 4; nt++) {
                    const int ng = nt >> 1, sel = nt & 1;
                    mma16816(acc[mt][nt], a_h[cur][mt],
                             b_l[cur][ng][sel], b_l[cur][ng][sel + 2]);
                }
            #pragma unroll
            for (int mt = 0; mt < 2; mt++)
                #pragma unroll
                for (int nt = 0; nt < 4; nt++) {
                    const int ng = nt >> 1, sel = nt & 1;
                    mma16816(acc[mt][nt], a_l[cur][mt],
                             b_h[cur][ng][sel], b_h[cur][ng][sel + 2]);
                }
        }
        __syncthreads();
    }

    // ---- epilogue ----
    const float alpha = scale ? __ldg(scale) : 1.0f;
    const int mrow = m0 + wm * 32 + (lane >> 2);
    #pragma unroll
    for (int mt = 0; mt < 2; mt++) {
        #pragma unroll
        for (int nt = 0; nt < 4; nt++) {
            const int n = n0 + wn * 32 + nt * 8 + 2 * (lane & 3);
            const float bv0 = bias ? bias[n]     : 0.0f;
            const float bv1 = bias ? bias[n + 1] : 0.0f;
            #pragma unroll
            for (int h = 0; h < 2; h++) {
                const long long m = (long long)(mrow + mt * 16 + h * 8);
                const float v0 = acc[mt][nt][2 * h + 0] * alpha + bv0;
                const float v1 = acc[mt][nt][2 * h + 1] * alpha + bv1;
                const size_t idx = (size_t)bz * sC + m * ldc + n;
                if (OUT_MODE == 0) {
                    *(float2*)(C + idx) = make_float2(v0, v1);
                } else {
                    bf16 h0 = __float2bfloat16(v0), h1 = __float2bfloat16(v1);
                    bf16 l0 = __float2bfloat16(v0 - __bfloat162float(h0));
                    bf16 l1 = __float2bfloat16(v1 - __bfloat162float(h1));
                    *(__nv_bfloat162*)(Ch + idx) = __nv_bfloat162(h0, h1);
                    *(__nv_bfloat162*)(Cl + idx) = __nv_bfloat162(l0, l1);
                }
            }
        }
    }
}

// ---------------- standalone GEMM kernels (GEMM2 / GEMM3) ----------------
template<int OUT_MODE, int LEN_MODE>
__global__ void __launch_bounds__(256, 2)
mma_gemm(const bf16* __restrict__ Ah, const bf16* __restrict__ Al, long long sA, int lda,
         const bf16* __restrict__ Bh, const bf16* __restrict__ Bl, long long sB, int ldb,
         float* __restrict__ C, bf16* __restrict__ Ch, bf16* __restrict__ Cl,
         long long sC, int ldc, int K,
         const float* __restrict__ bias, const float* __restrict__ scale,
         const int* __restrict__ lens)
{
    extern __shared__ char smem[];
    gemm_body<OUT_MODE, LEN_MODE>(smem, blockIdx.y * 128, blockIdx.x * 64, blockIdx.z,
                                  Ah, Al, sA, lda, Bh, Bl, sB, ldb,
                                  C, Ch, Cl, sC, ldc, K, bias, scale, lens);
}

// ---------------- fused GEMM1 + ksplit ----------------
// grid (8 + 32, 64): x<8 -> GEMM1 tile; x>=8 -> keys split 64x64 tile.
// ksplit linear id = (x-8) + 32*y in [0, 2048): 128 tiles/batch (16 k x 8 d).
#define G1X 8
#define KSX 32

__global__ void __launch_bounds__(256, 2)
gemm1_ksplit(const bf16* __restrict__ Ah, const bf16* __restrict__ Al, int lda,
             const bf16* __restrict__ Bh, const bf16* __restrict__ Bl, int ldb,
             bf16* __restrict__ Ch, bf16* __restrict__ Cl, int ldc, int K,
             const float* __restrict__ bias,
             const float* __restrict__ keys,
             bf16* __restrict__ kh, bf16* __restrict__ kl,
             bf16* __restrict__ th, bf16* __restrict__ tl)
{
    extern __shared__ char smem[];
    const int tid = threadIdx.x;

    if (blockIdx.x < G1X) {
        gemm_body<1, 0>(smem, blockIdx.y * 128, blockIdx.x * 64, 0,
                        Ah, Al, 0, lda, Bh, Bl, 0, ldb,
                        nullptr, Ch, Cl, 0, ldc, K, bias, nullptr, nullptr);
        return;
    }

    // ---- ksplit: 64x64 fp32 tile of keys[b] at (k0, d0) ----
    const int lin = (blockIdx.x - G1X) + KSX * blockIdx.y;   // 0..2047
    const int b  = lin >> 7;
    const int rem = lin & 127;
    const int k0 = (rem >> 3) << 6;
    const int d0 = (rem & 7) << 6;

    float* ts = (float*)smem;                  // [64][65]
    const float* xb = keys + (size_t)b * TK * DD;

    const int r  = tid >> 2;                   // 0..63
    const int cg = (tid & 3) << 4;             // 0,16,32,48

    const float* src = xb + (size_t)(k0 + r) * DD + d0 + cg;
    #pragma unroll
    for (int i = 0; i < 4; i++) {
        float4 v = ((const float4*)src)[i];
        const int cc = cg + i * 4;
        ts[r * 65 + cc + 0] = v.x; ts[r * 65 + cc + 1] = v.y;
        ts[r * 65 + cc + 2] = v.z; ts[r * 65 + cc + 3] = v.w;
        uint2 hu, lu;
        split4(v, hu, lu);
        const size_t o = (size_t)b * TK * DD + (size_t)(k0 + r) * DD + d0 + cc;
        *(uint2*)(kh + o) = hu;
        *(uint2*)(kl + o) = lu;
    }
    __syncthreads();

    // transposed writes: thread -> d-row, 16 consecutive k
    const int d  = tid >> 2;
    const int kg = (tid & 3) << 4;
    const size_t ot = (size_t)b * DD * TK + (size_t)(d0 + d) * TK + k0 + kg;
    #pragma unroll
    for (int i = 0; i < 4; i++) {
        float4 v;
        v.x = ts[(kg + i * 4 + 0) * 65 + d];
        v.y = ts[(kg + i * 4 + 1) * 65 + d];
        v.z = ts[(kg + i * 4 + 2) * 65 + d];
        v.w = ts[(kg + i * 4 + 3) * 65 + d];
        uint2 hu, lu;
        split4(v, hu, lu);
        *(uint2*)(th + ot + i * 4) = hu;
        *(uint2*)(tl + ot + i * 4) = lu;
    }
}

// ---------------- softmax: warp/row, masked, writes fp32 + split bf16 ----------------
__global__ void __launch_bounds__(128)
softmax_kernel(float* __restrict__ attn, const int* __restrict__ lens,
               bf16* __restrict__ ah, bf16* __restrict__ al)
{
    int warp = (int)((blockIdx.x * blockDim.x + threadIdx.x) >> 5);
    int lane = threadIdx.x & 31;
    if (warp >= B_ * TQ) return;
    const int len = lens[warp / TQ];
    float4* row = (float4*)(attn + (size_t)warp * TK);

    float4 v[8];
    float mx = -INFINITY;
    #pragma unroll
    for (int i = 0; i < 8; i++) {
        v[i] = row[i * 32 + lane];
        int k = 4 * (i * 32 + lane);
        if (k + 0 < len) mx = fmaxf(mx, v[i].x);
        if (k + 1 < len) mx = fmaxf(mx, v[i].y);
        if (k + 2 < len) mx = fmaxf(mx, v[i].z);
        if (k + 3 < len) mx = fmaxf(mx, v[i].w);
    }
    #pragma unroll
    for (int o = 16; o > 0; o >>= 1)
        mx = fmaxf(mx, __shfl_xor_sync(0xFFFFFFFFu, mx, o));

    float sum = 0.0f;
    #pragma unroll
    for (int i = 0; i < 8; i++) {
        int k = 4 * (i * 32 + lane);
        v[i].x = (k + 0 < len) ? expf(v[i].x - mx) : 0.0f;
        v[i].y = (k + 1 < len) ? expf(v[i].y - mx) : 0.0f;
        v[i].z = (k + 2 < len) ? expf(v[i].z - mx) : 0.0f;
        v[i].w = (k + 3 < len) ? expf(v[i].w - mx) : 0.0f;
        sum += v[i].x + v[i].y + v[i].z + v[i].w;
    }
    #pragma unroll
    for (int o = 16; o > 0; o >>= 1)
        sum += __shfl_xor_sync(0xFFFFFFFFu, sum, o);

    const float inv = 1.0f / sum;
    uint2* rh = (uint2*)(ah + (size_t)warp * TK);
    uint2* rl = (uint2*)(al + (size_t)warp * TK);
    #pragma unroll
    for (int i = 0; i < 8; i++) {
        v[i].x *= inv; v[i].y *= inv; v[i].z *= inv; v[i].w *= inv;
        row[i * 32 + lane] = v[i];
        uint2 hu, lu;
        split4(v[i], hu, lu);
        rh[i * 32 + lane] = hu;
        rl[i * 32 + lane] = lu;
    }
}

// ---------------- launch ----------------
extern "C" void kernel_launch(void* const* d_in, const int* in_sizes, int n_in,
                              void* d_out, int out_size)
{
    const float *query = nullptr, *keys = nullptr, *Wq = nullptr,
                *bq = nullptr, *scale = nullptr;
    const int *lens = nullptr;
    for (int i = 0; i < n_in; i++) {
        switch (in_sizes[i]) {
            case B_ * TQ * DD: query = (const float*)d_in[i]; break;
            case B_ * TK * DD: keys  = (const float*)d_in[i]; break;
            case B_:           lens  = (const int*)  d_in[i]; break;
            case DD * DD:      Wq    = (const float*)d_in[i]; break;
            case DD:           bq    = (const float*)d_in[i]; break;
            case 1:            scale = (const float*)d_in[i]; break;
            default: break;
        }
    }

    bf16 *qh, *ql, *wh, *wl, *kh, *kl, *kth, *ktl, *qph, *qpl, *ah, *al;
    cudaGetSymbolAddress((void**)&qh,  g_qh);  cudaGetSymbolAddress((void**)&ql,  g_ql);
    cudaGetSymbolAddress((void**)&wh,  g_wh);  cudaGetSymbolAddress((void**)&wl,  g_wl);
    cudaGetSymbolAddress((void**)&kh,  g_kh);  cudaGetSymbolAddress((void**)&kl,  g_kl);
    cudaGetSymbolAddress((void**)&kth, g_kth); cudaGetSymbolAddress((void**)&ktl, g_ktl);
    cudaGetSymbolAddress((void**)&qph, g_qph); cudaGetSymbolAddress((void**)&qpl, g_qpl);
    cudaGetSymbolAddress((void**)&ah,  g_ah);  cudaGetSymbolAddress((void**)&al,  g_al);

    cudaFuncSetAttribute(gemm1_ksplit, cudaFuncAttributeMaxDynamicSharedMemorySize, SMEM_DYN);
    cudaFuncSetAttribute(mma_gemm<0,1>, cudaFuncAttributeMaxDynamicSharedMemorySize, SMEM_DYN);
    cudaFuncSetAttribute(mma_gemm<0,2>, cudaFuncAttributeMaxDynamicSharedMemorySize, SMEM_DYN);

    float* context = (float*)d_out;                         // B*TQ*DD
    float* attn    = (float*)d_out + (size_t)B_ * TQ * DD;  // B*TQ*TK

    // query / Wq splits (GEMM1 inputs)
    split_kernel<<<(B_ * TQ * DD / 4 + 255) / 256, 256>>>(query, qh, ql, B_ * TQ * DD / 4);
    split_kernel<<<(DD * DD / 4 + 255) / 256, 256>>>(Wq, wh, wl, DD * DD / 4);

    // 1) GEMM1 (Q' = query @ Wq^T + bq -> split bf16) FUSED with keys split
    gemm1_ksplit<<<dim3(G1X + KSX, (B_ * TQ) / 128, 1), 256, SMEM_DYN>>>(
        qh, ql, DD, wh, wl, DD, qph, qpl, DD, DD, bq,
        keys, kh, kl, kth, ktl);

    // 2) scores = scale * Q'_b @ K_b^T -> fp32 attn; skip fully-masked N tiles
    mma_gemm<0,1><<<dim3(TK / 64, TQ / 128, B_), 256, SMEM_DYN>>>(
        qph, qpl, (long long)TQ * DD, DD,
        kh, kl, (long long)TK * DD, DD,
        attn, nullptr, nullptr, (long long)TQ * TK, TK, DD, nullptr, scale, lens);

    // 3) masked softmax (fp32 out + fused split; zeros all masked columns)
    softmax_kernel<<<(B_ * TQ * 32) / 128, 128>>>(attn, lens, ah, al);

    // 4) context = attn_b @ keysT_b^T -> fp32; truncate K to valid length
    mma_gemm<0,2><<<dim3(DD / 64, TQ / 128, B_), 256, SMEM_DYN>>>(
        ah, al, (long long)TQ * TK, TK,
        kth, ktl, (long long)DD * TK, TK,
        context, nullptr, nullptr, (long long)TQ * DD, DD, TK, nullptr, nullptr, lens);
}

// round 12
// speedup vs baseline: 1.0382x; 1.0192x over previous
#include <cuda_runtime.h>
#include <cuda_bf16.h>
#include <cstdint>
#include <math.h>

#define B_   16
#define TQ   512
#define TK   1024
#define DD   512

typedef __nv_bfloat16 bf16;

// ---------------- device scratch (no allocation allowed) ----------------
__device__ bf16 g_qh [(size_t)B_*TQ*DD], g_ql [(size_t)B_*TQ*DD];   // query split
__device__ bf16 g_wh [DD*DD],            g_wl [DD*DD];              // Wq split
__device__ bf16 g_kh [(size_t)B_*TK*DD], g_kl [(size_t)B_*TK*DD];   // keys split   [B,TK,DD]
__device__ bf16 g_kth[(size_t)B_*DD*TK], g_ktl[(size_t)B_*DD*TK];   // keys^T split [B,DD,TK]
__device__ bf16 g_qph[(size_t)B_*TQ*DD], g_qpl[(size_t)B_*TQ*DD];   // Q' split
__device__ bf16 g_ah [(size_t)B_*TQ*TK], g_al [(size_t)B_*TQ*TK];   // attn split

// ---------------- helpers ----------------
__device__ __forceinline__ uint32_t smem_u32(const void* p) {
    uint32_t a;
    asm("{ .reg .u64 t; cvta.to.shared.u64 t, %1; cvt.u32.u64 %0, t; }" : "=r"(a) : "l"(p));
    return a;
}
#define SW128(o) ((o) ^ (((o) >> 3) & 0x70))

__device__ __forceinline__ void cpa16(uint32_t dst, const void* src) {
    asm volatile("cp.async.cg.shared.global [%0], [%1], 16;" :: "r"(dst), "l"(src));
}
__device__ __forceinline__ void cpa_commit() {
    asm volatile("cp.async.commit_group;" ::: "memory");
}
__device__ __forceinline__ void ldsm4(uint32_t* r, uint32_t addr) {
    asm volatile("ldmatrix.sync.aligned.m8n8.x4.shared.b16 {%0,%1,%2,%3}, [%4];"
                 : "=r"(r[0]), "=r"(r[1]), "=r"(r[2]), "=r"(r[3]) : "r"(addr));
}
__device__ __forceinline__ void mma16816(float* d, const uint32_t* a,
                                         uint32_t b0, uint32_t b1) {
    asm volatile(
        "mma.sync.aligned.m16n8k16.row.col.f32.bf16.bf16.f32 "
        "{%0,%1,%2,%3}, {%4,%5,%6,%7}, {%8,%9}, {%0,%1,%2,%3};"
        : "+f"(d[0]), "+f"(d[1]), "+f"(d[2]), "+f"(d[3])
        : "r"(a[0]), "r"(a[1]), "r"(a[2]), "r"(a[3]), "r"(b0), "r"(b1));
}
__device__ __forceinline__ void split4(float4 v, uint2& hu, uint2& lu) {
    union { bf16 b[4]; uint2 u; } H, L;
    float xs[4] = {v.x, v.y, v.z, v.w};
    #pragma unroll
    for (int j = 0; j < 4; j++) {
        bf16 h = __float2bfloat16(xs[j]);
        H.b[j] = h;
        L.b[j] = __float2bfloat16(xs[j] - __bfloat162float(h));
    }
    hu = H.u; lu = L.u;
}

// ---------------- merged prep kernel ----------------
// Heterogeneous blocks, static smem only (no occupancy penalty):
//   bid < 2048           : keys 64x64 tile -> kh/kl + transposed kth/ktl
//   2048 <= bid < 6144   : query split (256 float4 per block)
//   6144 <= bid < 6400   : Wq split
#define KS_BLKS 2048
#define QS_BLKS 4096   // (B_*TQ*DD/4)/256
#define WS_BLKS 256    // (DD*DD/4)/256

__global__ void __launch_bounds__(256)
prep_kernel(const float* __restrict__ query, bf16* __restrict__ qh, bf16* __restrict__ ql,
            const float* __restrict__ Wq,    bf16* __restrict__ wh, bf16* __restrict__ wl,
            const float* __restrict__ keys,
            bf16* __restrict__ kh, bf16* __restrict__ kl,
            bf16* __restrict__ th, bf16* __restrict__ tl)
{
    __shared__ float ts[64 * 65];
    const int tid = threadIdx.x;
    const int bid = blockIdx.x;

    if (bid >= KS_BLKS) {
        // ---- flat splits ----
        if (bid < KS_BLKS + QS_BLKS) {
            int i = (bid - KS_BLKS) * 256 + tid;
            float4 v = ((const float4*)query)[i];
            uint2 hu, lu;
            split4(v, hu, lu);
            ((uint2*)qh)[i] = hu;
            ((uint2*)ql)[i] = lu;
        } else {
            int i = (bid - KS_BLKS - QS_BLKS) * 256 + tid;
            float4 v = ((const float4*)Wq)[i];
            uint2 hu, lu;
            split4(v, hu, lu);
            ((uint2*)wh)[i] = hu;
            ((uint2*)wl)[i] = lu;
        }
        return;
    }

    // ---- ksplit: 64x64 fp32 tile of keys[b] at (k0, d0); 128 tiles/batch ----
    const int b   = bid >> 7;
    const int rem = bid & 127;
    const int k0 = (rem >> 3) << 6;
    const int d0 = (rem & 7) << 6;

    const float* xb = keys + (size_t)b * TK * DD;
    const int r  = tid >> 2;                   // 0..63
    const int cg = (tid & 3) << 4;             // 0,16,32,48

    const float* src = xb + (size_t)(k0 + r) * DD + d0 + cg;
    #pragma unroll
    for (int i = 0; i < 4; i++) {
        float4 v = ((const float4*)src)[i];
        const int cc = cg + i * 4;
        ts[r * 65 + cc + 0] = v.x; ts[r * 65 + cc + 1] = v.y;
        ts[r * 65 + cc + 2] = v.z; ts[r * 65 + cc + 3] = v.w;
        uint2 hu, lu;
        split4(v, hu, lu);
        const size_t o = (size_t)b * TK * DD + (size_t)(k0 + r) * DD + d0 + cc;
        *(uint2*)(kh + o) = hu;
        *(uint2*)(kl + o) = lu;
    }
    __syncthreads();

    const int d  = tid >> 2;
    const int kg = (tid & 3) << 4;
    const size_t ot = (size_t)b * DD * TK + (size_t)(d0 + d) * TK + k0 + kg;
    #pragma unroll
    for (int i = 0; i < 4; i++) {
        float4 v;
        v.x = ts[(kg + i * 4 + 0) * 65 + d];
        v.y = ts[(kg + i * 4 + 1) * 65 + d];
        v.z = ts[(kg + i * 4 + 2) * 65 + d];
        v.w = ts[(kg + i * 4 + 3) * 65 + d];
        uint2 hu, lu;
        split4(v, hu, lu);
        *(uint2*)(th + ot + i * 4) = hu;
        *(uint2*)(tl + ot + i * 4) = lu;
    }
}

// ---------------- round-9-proven GEMM (BK=64, 2-stage, 2 CTAs/SM) ----------------
// C[m,n] = alpha * sum_k A[m,k]*B[n,k] (+bias[n]); A,B bf16 (hi,lo), k-contiguous.
// OUT_MODE 0: fp32 C. OUT_MODE 1: split-bf16 (Ch, Cl).
// LEN_MODE 0: none. 1: skip if n0 >= len. 2: truncate K to ceil64(len).
#define STAGE 49152          // Ah 16K | Al 16K | Bh 8K | Bl 8K
#define SMEM_DYN (2 * STAGE)

template<int OUT_MODE, int LEN_MODE>
__global__ void __launch_bounds__(256, 2)
mma_gemm(const bf16* __restrict__ Ah, const bf16* __restrict__ Al, long long sA, int lda,
         const bf16* __restrict__ Bh, const bf16* __restrict__ Bl, long long sB, int ldb,
         float* __restrict__ C, bf16* __restrict__ Ch, bf16* __restrict__ Cl,
         long long sC, int ldc, int K,
         const float* __restrict__ bias, const float* __restrict__ scale,
         const int* __restrict__ lens)
{
    extern __shared__ char smem[];
    const uint32_t sbase = smem_u32(smem);
    const int tid = threadIdx.x;

    const int m0 = blockIdx.y * 128, n0 = blockIdx.x * 64;
    const int bz = blockIdx.z;

    if (LEN_MODE == 1) {
        if (n0 >= lens[bz]) return;           // softmax zeros+overwrites this region
    }
    int Keff = K;
    if (LEN_MODE == 2) {
        Keff = (lens[bz] + 63) & ~63;         // attn == 0 beyond len: skip chunks
    }

    Ah += (long long)bz * sA;  Al += (long long)bz * sA;
    Bh += (long long)bz * sB;  Bl += (long long)bz * sB;

    const bf16* pAh = Ah + (size_t)m0 * lda;
    const bf16* pAl = Al + (size_t)m0 * lda;
    const bf16* pBh = Bh + (size_t)n0 * ldb;
    const bf16* pBl = Bl + (size_t)n0 * ldb;

    const int NC = Keff >> 6;

    auto load_chunk = [&](int c, int s) {
        const uint32_t base = sbase + s * STAGE;
        const size_t ck = (size_t)c * 64;
        #pragma unroll
        for (int i = 0; i < 4; i++) {              // A: 128 rows x 8 units
            int u = tid + i * 256;
            int row = u >> 3, c8 = u & 7;
            uint32_t off = SW128((uint32_t)((row << 7) | (c8 << 4)));
            const size_t g = (size_t)row * lda + ck + c8 * 8;
            cpa16(base +         off, pAh + g);
            cpa16(base + 16384 + off, pAl + g);
        }
        #pragma unroll
        for (int i = 0; i < 2; i++) {              // B: 64 rows x 8 units
            int u = tid + i * 256;
            int row = u >> 3, c8 = u & 7;
            uint32_t off = SW128((uint32_t)((row << 7) | (c8 << 4)));
            const size_t g = (size_t)row * ldb + ck + c8 * 8;
            cpa16(base + 32768 + off, pBh + g);
            cpa16(base + 40960 + off, pBl + g);
        }
        cpa_commit();
    };

    const int lane = tid & 31;
    const int wid = tid >> 5, wm = wid >> 1, wn = wid & 1;   // 4m x 2n
    const uint32_t arow = (uint32_t)(wm * 32 + (lane & 15));
    const uint32_t brow = (uint32_t)(wn * 32 + (lane & 15));
    const uint32_t chalf = (uint32_t)(lane >> 4);

    float acc[2][4][4];
    #pragma unroll
    for (int i = 0; i < 2; i++)
        #pragma unroll
        for (int j = 0; j < 4; j++)
            #pragma unroll
            for (int e = 0; e < 4; e++) acc[i][j][e] = 0.0f;

    uint32_t a_h[2][2][4], a_l[2][2][4], b_h[2][2][4], b_l[2][2][4];

    auto load_frags = [&](uint32_t SAh, uint32_t SAl, uint32_t SBh, uint32_t SBl,
                          int kt, int p) {
        const uint32_t ck16 = (uint32_t)((kt * 2 + chalf) << 4);
        #pragma unroll
        for (int mt = 0; mt < 2; mt++) {
            uint32_t off = SW128((uint32_t)(((arow + mt * 16) << 7) | ck16));
            ldsm4(a_h[p][mt], SAh + off);
            ldsm4(a_l[p][mt], SAl + off);
        }
        #pragma unroll
        for (int ng = 0; ng < 2; ng++) {
            uint32_t off = SW128((uint32_t)(((brow + ng * 16) << 7) | ck16));
            ldsm4(b_h[p][ng], SBh + off);
            ldsm4(b_l[p][ng], SBl + off);
        }
    };

    load_chunk(0, 0);

    for (int c = 0; c < NC; c++) {
        const int s = c & 1;
        if (c + 1 < NC) {
            load_chunk(c + 1, s ^ 1);
            asm volatile("cp.async.wait_group 1;" ::: "memory");
        } else {
            asm volatile("cp.async.wait_group 0;" ::: "memory");
        }
        __syncthreads();

        const uint32_t SAh = sbase + s * STAGE;
        const uint32_t SAl = SAh + 16384;
        const uint32_t SBh = SAh + 32768;
        const uint32_t SBl = SAh + 40960;

        load_frags(SAh, SAl, SBh, SBl, 0, 0);
        #pragma unroll
        for (int kt = 0; kt < 4; kt++) {
            const int cur = kt & 1;
            if (kt < 3) load_frags(SAh, SAl, SBh, SBl, kt + 1, cur ^ 1);
            #pragma unroll
            for (int mt = 0; mt < 2; mt++)
                #pragma unroll
                for (int nt = 0; nt < 4; nt++) {
                    const int ng = nt >> 1, sel = nt & 1;
                    mma16816(acc[mt][nt], a_h[cur][mt],
                             b_h[cur][ng][sel], b_h[cur][ng][sel + 2]);
                }
            #pragma unroll
            for (int mt = 0; mt < 2; mt++)
                #pragma unroll
                for (int nt = 0; nt < 4; nt++) {
                    const int ng = nt >> 1, sel = nt & 1;
                    mma16816(acc[mt][nt], a_h[cur][mt],
                             b_l[cur][ng][sel], b_l[cur][ng][sel + 2]);
                }
            #pragma unroll
            for (int mt = 0; mt < 2; mt++)
                #pragma unroll
                for (int nt = 0; nt < 4; nt++) {
                    const int ng = nt >> 1, sel = nt & 1;
                    mma16816(acc[mt][nt], a_l[cur][mt],
                             b_h[cur][ng][sel], b_h[cur][ng][sel + 2]);
                }
        }
        __syncthreads();
    }

    // ---- epilogue ----
    const float alpha = scale ? __ldg(scale) : 1.0f;
    const int mrow = m0 + wm * 32 + (lane >> 2);
    #pragma unroll
    for (int mt = 0; mt < 2; mt++) {
        #pragma unroll
        for (int nt = 0; nt < 4; nt++) {
            const int n = n0 + wn * 32 + nt * 8 + 2 * (lane & 3);
            const float bv0 = bias ? bias[n]     : 0.0f;
            const float bv1 = bias ? bias[n + 1] : 0.0f;
            #pragma unroll
            for (int h = 0; h < 2; h++) {
                const long long m = (long long)(mrow + mt * 16 + h * 8);
                const float v0 = acc[mt][nt][2 * h + 0] * alpha + bv0;
                const float v1 = acc[mt][nt][2 * h + 1] * alpha + bv1;
                const size_t idx = (size_t)bz * sC + m * ldc + n;
                if (OUT_MODE == 0) {
                    *(float2*)(C + idx) = make_float2(v0, v1);
                } else {
                    bf16 h0 = __float2bfloat16(v0), h1 = __float2bfloat16(v1);
                    bf16 l0 = __float2bfloat16(v0 - __bfloat162float(h0));
                    bf16 l1 = __float2bfloat16(v1 - __bfloat162float(h1));
                    *(__nv_bfloat162*)(Ch + idx) = __nv_bfloat162(h0, h1);
                    *(__nv_bfloat162*)(Cl + idx) = __nv_bfloat162(l0, l1);
                }
            }
        }
    }
}

// ---------------- softmax: warp/row, masked, length-aware chunk skipping ----------------
// Chunk i (of 8) covers k in [128i, 128(i+1)).
//  - load/exp only chunks with 128i < len (len >= 512 so i<4 always live)
//  - fp32 attn written for ALL k (zeros beyond len — part of the output)
//  - bf16 splits written only for chunks with 128i < ceil64(len): GEMM3's K-loop
//    stops at ceil64(len), so later split words are never read.
__global__ void __launch_bounds__(128)
softmax_kernel(float* __restrict__ attn, const int* __restrict__ lens,
               bf16* __restrict__ ah, bf16* __restrict__ al)
{
    int warp = (int)((blockIdx.x * blockDim.x + threadIdx.x) >> 5);
    int lane = threadIdx.x & 31;
    if (warp >= B_ * TQ) return;
    const int len = lens[warp / TQ];
    const int lpad = (len + 63) & ~63;
    float4* row = (float4*)(attn + (size_t)warp * TK);

    float4 v[8] = {};
    float mx = -INFINITY;
    #pragma unroll
    for (int i = 0; i < 8; i++) {
        if (i * 128 >= len) break;             // warp-uniform
        v[i] = row[i * 32 + lane];
        int k = 4 * (i * 32 + lane);
        if (k + 0 < len) mx = fmaxf(mx, v[i].x);
        if (k + 1 < len) mx = fmaxf(mx, v[i].y);
        if (k + 2 < len) mx = fmaxf(mx, v[i].z);
        if (k + 3 < len) mx = fmaxf(mx, v[i].w);
    }
    #pragma unroll
    for (int o = 16; o > 0; o >>= 1)
        mx = fmaxf(mx, __shfl_xor_sync(0xFFFFFFFFu, mx, o));

    float sum = 0.0f;
    #pragma unroll
    for (int i = 0; i < 8; i++) {
        if (i * 128 >= len) break;
        int k = 4 * (i * 32 + lane);
        v[i].x = (k + 0 < len) ? expf(v[i].x - mx) : 0.0f;
        v[i].y = (k + 1 < len) ? expf(v[i].y - mx) : 0.0f;
        v[i].z = (k + 2 < len) ? expf(v[i].z - mx) : 0.0f;
        v[i].w = (k + 3 < len) ? expf(v[i].w - mx) : 0.0f;
        sum += v[i].x + v[i].y + v[i].z + v[i].w;
    }
    #pragma unroll
    for (int o = 16; o > 0; o >>= 1)
        sum += __shfl_xor_sync(0xFFFFFFFFu, sum, o);

    const float inv = 1.0f / sum;
    uint2* rh = (uint2*)(ah + (size_t)warp * TK);
    uint2* rl = (uint2*)(al + (size_t)warp * TK);
    #pragma unroll
    for (int i = 0; i < 8; i++) {
        v[i].x *= inv; v[i].y *= inv; v[i].z *= inv; v[i].w *= inv;
        row[i * 32 + lane] = v[i];             // fp32 output: all 1024 cols
        if (i * 128 < lpad) {                  // splits: only what GEMM3 reads
            uint2 hu, lu;
            split4(v[i], hu, lu);
            rh[i * 32 + lane] = hu;
            rl[i * 32 + lane] = lu;
        }
    }
}

// ---------------- launch ----------------
extern "C" void kernel_launch(void* const* d_in, const int* in_sizes, int n_in,
                              void* d_out, int out_size)
{
    const float *query = nullptr, *keys = nullptr, *Wq = nullptr,
                *bq = nullptr, *scale = nullptr;
    const int *lens = nullptr;
    for (int i = 0; i < n_in; i++) {
        switch (in_sizes[i]) {
            case B_ * TQ * DD: query = (const float*)d_in[i]; break;
            case B_ * TK * DD: keys  = (const float*)d_in[i]; break;
            case B_:           lens  = (const int*)  d_in[i]; break;
            case DD * DD:      Wq    = (const float*)d_in[i]; break;
            case DD:           bq    = (const float*)d_in[i]; break;
            case 1:            scale = (const float*)d_in[i]; break;
            default: break;
        }
    }

    bf16 *qh, *ql, *wh, *wl, *kh, *kl, *kth, *ktl, *qph, *qpl, *ah, *al;
    cudaGetSymbolAddress((void**)&qh,  g_qh);  cudaGetSymbolAddress((void**)&ql,  g_ql);
    cudaGetSymbolAddress((void**)&wh,  g_wh);  cudaGetSymbolAddress((void**)&wl,  g_wl);
    cudaGetSymbolAddress((void**)&kh,  g_kh);  cudaGetSymbolAddress((void**)&kl,  g_kl);
    cudaGetSymbolAddress((void**)&kth, g_kth); cudaGetSymbolAddress((void**)&ktl, g_ktl);
    cudaGetSymbolAddress((void**)&qph, g_qph); cudaGetSymbolAddress((void**)&qpl, g_qpl);
    cudaGetSymbolAddress((void**)&ah,  g_ah);  cudaGetSymbolAddress((void**)&al,  g_al);

    cudaFuncSetAttribute(mma_gemm<1,0>, cudaFuncAttributeMaxDynamicSharedMemorySize, SMEM_DYN);
    cudaFuncSetAttribute(mma_gemm<0,1>, cudaFuncAttributeMaxDynamicSharedMemorySize, SMEM_DYN);
    cudaFuncSetAttribute(mma_gemm<0,2>, cudaFuncAttributeMaxDynamicSharedMemorySize, SMEM_DYN);

    float* context = (float*)d_out;                         // B*TQ*DD
    float* attn    = (float*)d_out + (size_t)B_ * TQ * DD;  // B*TQ*TK

    // 0) merged prep: keys split+transpose, query split, Wq split (one launch)
    prep_kernel<<<KS_BLKS + QS_BLKS + WS_BLKS, 256>>>(
        query, qh, ql, Wq, wh, wl, keys, kh, kl, kth, ktl);

    // 1) Q' = query @ Wq^T + bq -> split bf16 directly (M=8192, N=512, K=512)
    mma_gemm<1,0><<<dim3(DD / 64, (B_ * TQ) / 128, 1), 256, SMEM_DYN>>>(
        qh, ql, 0, DD, wh, wl, 0, DD,
        nullptr, qph, qpl, 0, DD, DD, bq, nullptr, nullptr);

    // 2) scores = scale * Q'_b @ K_b^T -> fp32 attn; skip fully-masked N tiles
    mma_gemm<0,1><<<dim3(TK / 64, TQ / 128, B_), 256, SMEM_DYN>>>(
        qph, qpl, (long long)TQ * DD, DD,
        kh, kl, (long long)TK * DD, DD,
        attn, nullptr, nullptr, (long long)TQ * TK, TK, DD, nullptr, scale, lens);

    // 3) masked softmax (fp32 out + fused split; length-aware skipping)
    softmax_kernel<<<(B_ * TQ * 32) / 128, 128>>>(attn, lens, ah, al);

    // 4) context = attn_b @ keysT_b^T -> fp32; truncate K to valid length
    mma_gemm<0,2><<<dim3(DD / 64, TQ / 128, B_), 256, SMEM_DYN>>>(
        ah, al, (long long)TQ * TK, TK,
        kth, ktl, (long long)DD * TK, TK,
        context, nullptr, nullptr, (long long)TQ * DD, DD, TK, nullptr, nullptr, lens);
}